// round 11
// baseline (speedup 1.0000x reference)
#include <cuda_runtime.h>
#include <cuda_fp16.h>
#include <cstdint>
#include <cstddef>

// ---------------------------------------------------------------------------
// Problem constants
// ---------------------------------------------------------------------------
#define N_NODES 100
#define IN_C    65536
#define OUT_C   60
#define N_EDGES 1600
#define NSPLIT  96
#define KTILE   64
#define GTHREADS 256

typedef unsigned int u32;

// ---------------------------------------------------------------------------
// smem word-layout (per stage, 32-bit words). Rows padded to 72 fp16
// (36 words, 144 B): 16B-aligned ldmatrix rows, conflict-free.
//   A tiles: 128 rows x 36 words = 4608 words each (hi, lo)
//   B tile : 128 rows x 36 words = 4608 words (2 heads x 64 cols, fp16 W)
// ---------------------------------------------------------------------------
#define AROW_W  36
#define AHI_W   0
#define ALO_W   4608
#define BW_W    9216
#define STAGE_W 13824
#define SMEM_W  (2 * STAGE_W)
#define SMEM_B  (SMEM_W * 4)        // 110592 B -> 2 blocks/SM (221 KB)

__device__ __forceinline__ u32 smem_addr_u32(const void* p) {
    u32 a;
    asm("{ .reg .u64 t; cvta.to.shared.u64 t, %1; cvt.u32.u64 %0, t; }"
        : "=r"(a) : "l"(p));
    return a;
}
__device__ __forceinline__ void cpasync16(u32 dst, const void* src) {
    asm volatile("cp.async.cg.shared.global [%0], [%1], 16;"
                 :: "r"(dst), "l"(src) : "memory");
}
#define CPASYNC_COMMIT() asm volatile("cp.async.commit_group;" ::: "memory")
#define CPASYNC_WAIT()   asm volatile("cp.async.wait_group 0;" ::: "memory")

// mma.sync m16n8k16 row.col f32.f16.f16.f32  (fast path — keep f32 acc!)
__device__ __forceinline__ void mma16816(float* c, const u32* a, const u32* b) {
    asm volatile(
        "mma.sync.aligned.m16n8k16.row.col.f32.f16.f16.f32 "
        "{%0,%1,%2,%3}, {%4,%5,%6,%7}, {%8,%9}, {%0,%1,%2,%3};"
        : "+f"(c[0]), "+f"(c[1]), "+f"(c[2]), "+f"(c[3])
        : "r"(a[0]), "r"(a[1]), "r"(a[2]), "r"(a[3]), "r"(b[0]), "r"(b[1]));
}

#define LDSM4(r, addr) \
    asm volatile("ldmatrix.sync.aligned.m8n8.x4.shared.b16 {%0,%1,%2,%3}, [%4];" \
        : "=r"((r)[0]), "=r"((r)[1]), "=r"((r)[2]), "=r"((r)[3]) : "r"(addr))

// ---------------------------------------------------------------------------
// Scratch
// ---------------------------------------------------------------------------
__device__ u32   g_Xh[IN_C * N_NODES / 2];   // x hi, fp16 pairs (13.1 MB)
__device__ u32   g_Xl[IN_C * N_NODES / 2];   // x lo residual, fp16 pairs
__device__ float g_Yt[360 * 100];            // transposed Y copy 0
__device__ float g_Yt2[360 * 100];           // transposed Y copy 1
__device__ float g_A[10000];                 // normalized adjacency (Â)
__device__ float g_M2[10000];                // 2Â² − I
__device__ float g_emb[2 * 6000];
__device__ float g_V[120];

// ---------------------------------------------------------------------------
// Kernel 0: split X into fp16 hi/lo; first 71 blocks zero both Yt copies
// ---------------------------------------------------------------------------
__global__ void xsplit_kernel(const float* __restrict__ x) {
    int idx = blockIdx.x * 256 + threadIdx.x;       // 1,638,400 float4
    if (blockIdx.x < 71) {
        int z = blockIdx.x * 256 + threadIdx.x;
        if (z < 9000)                    ((float4*)g_Yt)[z]         = make_float4(0.f, 0.f, 0.f, 0.f);
        else if (z < 18000)              ((float4*)g_Yt2)[z - 9000] = make_float4(0.f, 0.f, 0.f, 0.f);
    }
    float4 v = ((const float4*)x)[idx];
    __half h0 = __float2half_rn(v.x), h1 = __float2half_rn(v.y);
    __half h2 = __float2half_rn(v.z), h3 = __float2half_rn(v.w);
    __half l0 = __float2half_rn(v.x - __half2float(h0));
    __half l1 = __float2half_rn(v.y - __half2float(h1));
    __half l2 = __float2half_rn(v.z - __half2float(h2));
    __half l3 = __float2half_rn(v.w - __half2float(h3));
    __half2 hp01 = __halves2half2(h0, h1), hp23 = __halves2half2(h2, h3);
    __half2 lp01 = __halves2half2(l0, l1), lp23 = __halves2half2(l2, l3);
    ((uint2*)g_Xh)[idx] = make_uint2(*(u32*)&hp01, *(u32*)&hp23);
    ((uint2*)g_Xl)[idx] = make_uint2(*(u32*)&lp01, *(u32*)&lp23);
}

// ---------------------------------------------------------------------------
// Kernel 1: prep — Â, M2 = 2Â²−I, vnr sums, init out with biases
// ---------------------------------------------------------------------------
__global__ void prep_kernel(const int* __restrict__ ei,
                            const float* __restrict__ vnr,
                            const float* __restrict__ avw, const float* __restrict__ avb,
                            const float* __restrict__ cvw, const float* __restrict__ cvb,
                            const float* __restrict__ afb, const float* __restrict__ cfb,
                            float* __restrict__ out, int out_size) {
    __shared__ float sA[10000];
    __shared__ float sdeg[N_NODES];
    const int t = threadIdx.x;  // 1024

    for (int i = t; i < 10000; i += 1024) sA[i] = 0.f;
    if (t < N_NODES) sdeg[t] = 0.f;
    __syncthreads();

    for (int e = t; e < N_EDGES; e += 1024) atomicAdd(&sdeg[ei[e]], 1.f);
    __syncthreads();
    if (t < N_NODES) {
        float d = sdeg[t];
        sdeg[t] = (d > 0.f) ? rsqrtf(fmaxf(d, 1.f)) : 0.f;
    }
    __syncthreads();
    for (int e = t; e < N_EDGES; e += 1024) {
        int s = ei[e];
        int d = ei[N_EDGES + e];
        atomicAdd(&sA[d * N_NODES + s], -sdeg[s] * sdeg[d]);
    }
    __syncthreads();
    for (int i = t; i < 10000; i += 1024) g_A[i] = sA[i];

    // M2 = 2 Â Â − I   (smem matmul)
    for (int idx = t; idx < 10000; idx += 1024) {
        int i = idx / 100, j = idx - 100 * i;
        float a0 = 0.f, a1 = 0.f;
        #pragma unroll 10
        for (int k = 0; k < N_NODES; k += 2) {
            a0 = fmaf(sA[i * 100 + k],     sA[k * 100 + j],       a0);
            a1 = fmaf(sA[i * 100 + k + 1], sA[(k + 1) * 100 + j], a1);
        }
        g_M2[idx] = 2.f * (a0 + a1) - (i == j ? 1.f : 0.f);
    }

    if (t < OUT_C) {
        float va = 0.f, vc = 0.f;
        #pragma unroll
        for (int i = 0; i < 3; i++) {
            float v = vnr[i];
            va += v * avw[i * OUT_C + t] + avb[i * OUT_C + t];
            vc += v * cvw[i * OUT_C + t] + cvb[i * OUT_C + t];
        }
        g_V[t] = va;
        g_V[OUT_C + t] = vc;
    }

    for (int j = t; j < out_size; j += 1024)
        out[j] = (j < 100) ? afb[j] : ((j == 100) ? cfb[0] : 0.f);
}

// ---------------------------------------------------------------------------
// A-tile staging via 16B cp.async (Xh/Xl already fp16 in gmem)
// ---------------------------------------------------------------------------
__device__ __forceinline__ void stage_A_async(u32 buf, int kb, int t) {
    #pragma unroll
    for (int i = 0; i < 4; i++) {
        int idx = t + i * GTHREADS;
        if (idx < 800) {
            int m = idx >> 3, q = idx & 7;          // q = 16B chunk
            size_t w = (size_t)m * (IN_C / 2) + (kb >> 1) + q * 4;
            u32 d = buf + (u32)((m * AROW_W + q * 4) * 4);
            cpasync16(d, g_Xh + w);
            cpasync16(d + ALO_W * 4, g_Xl + w);
        }
    }
    CPASYNC_COMMIT();
}

// W half-stage: load one head's W slab into 15 regs (3840 = 256*15 exactly)
__device__ __forceinline__ void load_W(float* wr, const float* Wh, int kb, int t) {
    #pragma unroll
    for (int i = 0; i < 15; i++) {
        int idx = t + i * GTHREADS;
        int k = idx / OUT_C, ch = idx - k * OUT_C;
        wr[i] = Wh[(size_t)(kb + k) * OUT_C + ch];
    }
}
__device__ __forceinline__ void store_W(const float* wr, u32* sb, int h, int t) {
    #pragma unroll
    for (int i = 0; i < 15; i++) {
        int idx = t + i * GTHREADS;
        int k = idx / OUT_C, ch = idx - k * OUT_C;
        ((__half*)(sb + BW_W))[(h * 64 + ch) * 72 + k] = __float2half_rn(wr[i]);
    }
}

// ---------------------------------------------------------------------------
// Kernel 2: fp16 2-term GEMM, two heads fused per block (B = 128 rows)
//   grid (96, 3 orders); 256 thr = 8 warps (4m x 2n), warp tile 32m x 64n
//   f32 accumulators both terms (R10 lesson); occ 2; dual-Yt split-K
// ---------------------------------------------------------------------------
__global__ __launch_bounds__(GTHREADS, 2)
void gemm_mma(const float* __restrict__ aw,
              const float* __restrict__ cw) {
    extern __shared__ u32 smw[];
    const int t = threadIdx.x;
    const int lane = t & 31, wid = t >> 5;
    const int wm = wid >> 1, wn = wid & 1;
    const bool do_mt1 = (wm < 3);          // rows 112-127: all pad
    const int g = blockIdx.y;              // cheb order
    const float* W0 = aw + (size_t)g * IN_C * OUT_C;
    const float* W1 = cw + (size_t)g * IN_C * OUT_C;

    int k0 = (int)(((long long)blockIdx.x * IN_C) / NSPLIT) & ~(KTILE - 1);
    int k1 = (int)(((long long)(blockIdx.x + 1) * IN_C) / NSPLIT) & ~(KTILE - 1);
    const int nch = (k1 - k0) / KTILE;

    float acc[2][8][4];
    #pragma unroll
    for (int mt = 0; mt < 2; mt++)
        #pragma unroll
        for (int nt = 0; nt < 8; nt++)
            #pragma unroll
            for (int q = 0; q < 4; q++) acc[mt][nt][q] = 0.f;

    const u32 sbase = smem_addr_u32(smw);
    const int t2 = lane >> 3, rr = lane & 7;
    const u32 a_off = (u32)(((wm * 32 + rr + (t2 & 1) * 8) * AROW_W + (t2 >> 1) * 4) * 4);
    const u32 b_off = (u32)(BW_W * 4) +
                      (u32)(((wn * 64 + rr + (t2 >> 1) * 8) * AROW_W + (t2 & 1) * 4) * 4);

    float wr[15];

    // ---- preamble: stage 0
    stage_A_async(sbase, k0, t);
    load_W(wr, W0, k0, t);
    store_W(wr, smw, 0, t);
    load_W(wr, W1, k0, t);
    store_W(wr, smw, 1, t);
    CPASYNC_WAIT();
    __syncthreads();

    for (int c = 0; c < nch; c++) {
        const u32 stb = sbase + ((c & 1) ? STAGE_W * 4 : 0);
        u32* stn = smw + ((c & 1) ? 0 : STAGE_W);
        const bool more = (c + 1 < nch);
        const int kb1 = k0 + (c + 1) * KTILE;

        if (more) {
            stage_A_async(sbase + ((c & 1) ? 0 : STAGE_W * 4), kb1, t);
            load_W(wr, W0, kb1, t);
        }

        // ---- kc 0,1
        #pragma unroll
        for (int kc = 0; kc < 2; kc++) {
            const u32 ko = kc * 32;
            u32 ah0[4], ah1[4], al0[4], al1[4];
            u32 b0[4], b1[4], b2[4], b3[4];
            LDSM4(ah0, stb + a_off + ko);
            if (do_mt1) LDSM4(ah1, stb + a_off + 2304 + ko);
            LDSM4(al0, stb + a_off + 18432 + ko);
            if (do_mt1) LDSM4(al1, stb + a_off + 18432 + 2304 + ko);
            LDSM4(b0, stb + b_off + ko);
            LDSM4(b1, stb + b_off + 2304 + ko);
            LDSM4(b2, stb + b_off + 4608 + ko);
            LDSM4(b3, stb + b_off + 6912 + ko);
            const u32* bh[8] = { b0, b0 + 2, b1, b1 + 2, b2, b2 + 2, b3, b3 + 2 };
            #pragma unroll
            for (int nt = 0; nt < 8; nt++) {
                mma16816(acc[0][nt], ah0, bh[nt]);
                mma16816(acc[0][nt], al0, bh[nt]);
                if (do_mt1) {
                    mma16816(acc[1][nt], ah1, bh[nt]);
                    mma16816(acc[1][nt], al1, bh[nt]);
                }
            }
        }

        if (more) {
            store_W(wr, stn, 0, t);
            load_W(wr, W1, kb1, t);
        }

        // ---- kc 2,3
        #pragma unroll
        for (int kc = 2; kc < 4; kc++) {
            const u32 ko = kc * 32;
            u32 ah0[4], ah1[4], al0[4], al1[4];
            u32 b0[4], b1[4], b2[4], b3[4];
            LDSM4(ah0, stb + a_off + ko);
            if (do_mt1) LDSM4(ah1, stb + a_off + 2304 + ko);
            LDSM4(al0, stb + a_off + 18432 + ko);
            if (do_mt1) LDSM4(al1, stb + a_off + 18432 + 2304 + ko);
            LDSM4(b0, stb + b_off + ko);
            LDSM4(b1, stb + b_off + 2304 + ko);
            LDSM4(b2, stb + b_off + 4608 + ko);
            LDSM4(b3, stb + b_off + 6912 + ko);
            const u32* bh[8] = { b0, b0 + 2, b1, b1 + 2, b2, b2 + 2, b3, b3 + 2 };
            #pragma unroll
            for (int nt = 0; nt < 8; nt++) {
                mma16816(acc[0][nt], ah0, bh[nt]);
                mma16816(acc[0][nt], al0, bh[nt]);
                if (do_mt1) {
                    mma16816(acc[1][nt], ah1, bh[nt]);
                    mma16816(acc[1][nt], al1, bh[nt]);
                }
            }
        }

        if (more) {
            store_W(wr, stn, 1, t);
            CPASYNC_WAIT();
        }
        __syncthreads();
    }

    // ---- epilogue: atomicAdd into dual Yt (parity selects copy)
    const int r = lane >> 2, cb = (lane & 3) * 2;
    float* Ysel = (blockIdx.x & 1) ? g_Yt2 : g_Yt;
    #pragma unroll
    for (int mt = 0; mt < 2; mt++) {
        if (mt == 1 && !do_mt1) break;
        int row = wm * 32 + mt * 16 + r;
        #pragma unroll
        for (int nt = 0; nt < 8; nt++) {
            int col = wn * 64 + nt * 8 + cb;      // 0..127 = h*64+ch
            int h = col >> 6, ch = col & 63;
            float* dst = Ysel + ((h * 3 + g) * 60 + ch) * 100;
            if (ch < OUT_C) {
                if (row < N_NODES)     atomicAdd(dst + row,     acc[mt][nt][0]);
                if (row + 8 < N_NODES) atomicAdd(dst + row + 8, acc[mt][nt][2]);
            }
            if (ch + 1 < OUT_C) {
                if (row < N_NODES)     atomicAdd(dst + 100 + row,     acc[mt][nt][1]);
                if (row + 8 < N_NODES) atomicAdd(dst + 100 + row + 8, acc[mt][nt][3]);
            }
        }
    }
}

// ---------------------------------------------------------------------------
// Kernel 3: emb. 120 blocks x 256 thr; Â and M2 staged in smem (pitch 101).
//   emb[:,h,c] = tanh(y0 + Â·y1 + M2·y2 + b) + vnr; Y = Yt + Yt2
// ---------------------------------------------------------------------------
#define EMB_SMEM ((2 * 100 * 101 + 200) * 4)
__global__ __launch_bounds__(256)
void emb6_kernel(const float* __restrict__ acb,
                 const float* __restrict__ ccb) {
    extern __shared__ float es[];
    float* sA  = es;
    float* sM  = es + 10100;
    float* y1s = es + 20200;
    float* y2s = es + 20300;
    const int b = blockIdx.x, t = threadIdx.x;
    const int h = b / OUT_C, c = b - OUT_C * h;

    for (int i = t; i < 2500; i += 256) {
        float4 v = ((const float4*)g_A)[i];
        int r = i / 25, q = i - r * 25;
        float* dst = sA + r * 101 + q * 4;
        dst[0] = v.x; dst[1] = v.y; dst[2] = v.z; dst[3] = v.w;
    }
    for (int i = t; i < 2500; i += 256) {
        float4 v = ((const float4*)g_M2)[i];
        int r = i / 25, q = i - r * 25;
        float* dst = sM + r * 101 + q * 4;
        dst[0] = v.x; dst[1] = v.y; dst[2] = v.z; dst[3] = v.w;
    }
    if (t < N_NODES) {
        int o1 = (h * 180 + 60 + c) * 100 + t;
        int o2 = (h * 180 + 120 + c) * 100 + t;
        y1s[t] = g_Yt[o1] + g_Yt2[o1];
        y2s[t] = g_Yt[o2] + g_Yt2[o2];
    }
    __syncthreads();

    if (t < N_NODES) {
        const float* Ar = sA + t * 101;
        const float* Mr = sM + t * 101;
        float a0 = 0.f, a1 = 0.f;
        #pragma unroll 10
        for (int s = 0; s < N_NODES; s += 2) {
            a0 = fmaf(Ar[s],     y1s[s],     a0);
            a1 = fmaf(Ar[s + 1], y1s[s + 1], a1);
            a0 = fmaf(Mr[s],     y2s[s],     a0);
            a1 = fmaf(Mr[s + 1], y2s[s + 1], a1);
        }
        int o0 = (h * 180 + c) * 100 + t;
        float y0v = g_Yt[o0] + g_Yt2[o0];
        float pre = y0v + a0 + a1 + (h ? ccb[c] : acb[c]);
        g_emb[h * 6000 + t * OUT_C + c] = tanhf(pre) + g_V[h * OUT_C + c];
    }
}

// ---------------------------------------------------------------------------
// Kernel 4: heads. 120 blocks x 128 threads, 50 rows each of the 6000-dot
// ---------------------------------------------------------------------------
__global__ void fc_kernel(const float* __restrict__ afw,
                          const float* __restrict__ cfw,
                          float* __restrict__ out, int out_size) {
    __shared__ float ea[50], ec[50];
    __shared__ float red[4];
    const int b = blockIdx.x, t = threadIdx.x;
    const int i0 = b * 50;

    if (t < 50) {
        ea[t] = g_emb[i0 + t];
        ec[t] = g_emb[6000 + i0 + t];
    }
    __syncthreads();

    if (t < 100) {
        float a0 = 0.f, a1 = 0.f;
        #pragma unroll 5
        for (int i = 0; i < 50; i += 2) {
            a0 = fmaf(ea[i],     afw[(size_t)(i0 + i) * 100 + t],     a0);
            a1 = fmaf(ea[i + 1], afw[(size_t)(i0 + i + 1) * 100 + t], a1);
        }
        atomicAdd(&out[t], a0 + a1);
    }

    float v = (t < 50) ? ec[t] * cfw[i0 + t] : 0.f;
    #pragma unroll
    for (int off = 16; off > 0; off >>= 1)
        v += __shfl_down_sync(0xffffffffu, v, off);
    if ((t & 31) == 0) red[t >> 5] = v;
    __syncthreads();
    if (t == 0 && out_size > 100)
        atomicAdd(&out[100], red[0] + red[1] + red[2] + red[3]);
}

// ---------------------------------------------------------------------------
// Launch
// ---------------------------------------------------------------------------
extern "C" void kernel_launch(void* const* d_in, const int* in_sizes, int n_in,
                              void* d_out, int out_size) {
    const float* x   = (const float*)d_in[0];
    const int*   ei  = (const int*)  d_in[1];
    const float* vnr = (const float*)d_in[2];
    const float* aw  = (const float*)d_in[3];
    const float* acb = (const float*)d_in[4];
    const float* cw  = (const float*)d_in[5];
    const float* ccb = (const float*)d_in[6];
    const float* avw = (const float*)d_in[7];
    const float* avb = (const float*)d_in[8];
    const float* cvw = (const float*)d_in[9];
    const float* cvb = (const float*)d_in[10];
    const float* afw = (const float*)d_in[11];
    const float* afb = (const float*)d_in[12];
    const float* cfw = (const float*)d_in[13];
    const float* cfb = (const float*)d_in[14];
    float* out = (float*)d_out;

    static int smem_set = 0;
    if (!smem_set) {
        cudaFuncSetAttribute(gemm_mma, cudaFuncAttributeMaxDynamicSharedMemorySize, SMEM_B);
        cudaFuncSetAttribute(emb6_kernel, cudaFuncAttributeMaxDynamicSharedMemorySize, EMB_SMEM);
        smem_set = 1;
    }

    xsplit_kernel<<<6400, 256>>>(x);
    prep_kernel<<<1, 1024>>>(ei, vnr, avw, avb, cvw, cvb, afb, cfb, out, out_size);
    gemm_mma<<<dim3(NSPLIT, 3), GTHREADS, SMEM_B>>>(aw, cw);
    emb6_kernel<<<120, 256, EMB_SMEM>>>(acb, ccb);
    fc_kernel<<<120, 128>>>(afw, cfw, out, out_size);
}

// round 12
// speedup vs baseline: 2.0227x; 2.0227x over previous
#include <cuda_runtime.h>
#include <cuda_fp16.h>
#include <cstdint>
#include <cstddef>

// ---------------------------------------------------------------------------
// Problem constants
// ---------------------------------------------------------------------------
#define N_NODES 100
#define IN_C    65536
#define OUT_C   60
#define N_EDGES 1600
#define NSPLIT  48
#define KTILE   64
#define GTHREADS 256

typedef unsigned int u32;

// ---------------------------------------------------------------------------
// smem word-layout (per stage, 32-bit words). Rows padded to 72 fp16
// (36 words, 144 B): 16B-aligned ldmatrix rows, conflict-free.
//   A tiles: 128 rows x 36 words = 4608 words each (hi, lo)
//   B tile :  64 rows x 36 words = 2304 words (fp16 W)
// ---------------------------------------------------------------------------
#define AROW_W  36
#define AHI_W   0
#define ALO_W   4608
#define BHI_W   9216
#define STAGE_W 11520
#define SMEM_W  (2 * STAGE_W)
#define SMEM_B  (SMEM_W * 4)        // 92160 bytes -> 2 blocks/SM

__device__ __forceinline__ u32 smem_addr_u32(const void* p) {
    u32 a;
    asm("{ .reg .u64 t; cvta.to.shared.u64 t, %1; cvt.u32.u64 %0, t; }"
        : "=r"(a) : "l"(p));
    return a;
}
__device__ __forceinline__ void cpasync16(u32 dst, const void* src) {
    asm volatile("cp.async.cg.shared.global [%0], [%1], 16;"
                 :: "r"(dst), "l"(src) : "memory");
}
#define CPASYNC_COMMIT() asm volatile("cp.async.commit_group;" ::: "memory")
#define CPASYNC_WAIT()   asm volatile("cp.async.wait_group 0;" ::: "memory")

// mma.sync m16n8k16 row.col f32.f16.f16.f32  (fast path — f32 acc only)
__device__ __forceinline__ void mma16816(float* c, const u32* a, const u32* b) {
    asm volatile(
        "mma.sync.aligned.m16n8k16.row.col.f32.f16.f16.f32 "
        "{%0,%1,%2,%3}, {%4,%5,%6,%7}, {%8,%9}, {%0,%1,%2,%3};"
        : "+f"(c[0]), "+f"(c[1]), "+f"(c[2]), "+f"(c[3])
        : "r"(a[0]), "r"(a[1]), "r"(a[2]), "r"(a[3]), "r"(b[0]), "r"(b[1]));
}

#define LDSM4(r, addr) \
    asm volatile("ldmatrix.sync.aligned.m8n8.x4.shared.b16 {%0,%1,%2,%3}, [%4];" \
        : "=r"((r)[0]), "=r"((r)[1]), "=r"((r)[2]), "=r"((r)[3]) : "r"(addr))

// ---------------------------------------------------------------------------
// Scratch
// ---------------------------------------------------------------------------
__device__ u32   g_Xh[IN_C * N_NODES / 2];   // x hi, fp16 pairs (13.1 MB)
__device__ u32   g_Xl[IN_C * N_NODES / 2];   // x lo residual, fp16 pairs
__device__ float g_Yt[360 * 100];            // transposed Y: [col][node]
__device__ float g_A[10000];                 // normalized adjacency (Â)
__device__ float g_emb[2 * 6000];
__device__ float g_V[120];

// ---------------------------------------------------------------------------
// Kernel 0: split X into fp16 hi/lo; first 36 blocks also zero Yt
// ---------------------------------------------------------------------------
__global__ void xsplit_kernel(const float* __restrict__ x) {
    int idx = blockIdx.x * 256 + threadIdx.x;       // 1,638,400 float4
    if (blockIdx.x < 36) {
        int z = blockIdx.x * 256 + threadIdx.x;
        if (z < 9000) ((float4*)g_Yt)[z] = make_float4(0.f, 0.f, 0.f, 0.f);
    }
    float4 v = ((const float4*)x)[idx];
    __half h0 = __float2half_rn(v.x), h1 = __float2half_rn(v.y);
    __half h2 = __float2half_rn(v.z), h3 = __float2half_rn(v.w);
    __half l0 = __float2half_rn(v.x - __half2float(h0));
    __half l1 = __float2half_rn(v.y - __half2float(h1));
    __half l2 = __float2half_rn(v.z - __half2float(h2));
    __half l3 = __float2half_rn(v.w - __half2float(h3));
    __half2 hp01 = __halves2half2(h0, h1), hp23 = __halves2half2(h2, h3);
    __half2 lp01 = __halves2half2(l0, l1), lp23 = __halves2half2(l2, l3);
    ((uint2*)g_Xh)[idx] = make_uint2(*(u32*)&hp01, *(u32*)&hp23);
    ((uint2*)g_Xl)[idx] = make_uint2(*(u32*)&lp01, *(u32*)&lp23);
}

// ---------------------------------------------------------------------------
// Kernel 1: prep — Â, vnr sums, init out with biases (no M2)
// ---------------------------------------------------------------------------
__global__ void prep_kernel(const int* __restrict__ ei,
                            const float* __restrict__ vnr,
                            const float* __restrict__ avw, const float* __restrict__ avb,
                            const float* __restrict__ cvw, const float* __restrict__ cvb,
                            const float* __restrict__ afb, const float* __restrict__ cfb,
                            float* __restrict__ out, int out_size) {
    __shared__ float sA[10000];
    __shared__ float sdeg[N_NODES];
    const int t = threadIdx.x;  // 1024

    for (int i = t; i < 10000; i += 1024) sA[i] = 0.f;
    if (t < N_NODES) sdeg[t] = 0.f;
    __syncthreads();

    for (int e = t; e < N_EDGES; e += 1024) atomicAdd(&sdeg[ei[e]], 1.f);
    __syncthreads();
    if (t < N_NODES) {
        float d = sdeg[t];
        sdeg[t] = (d > 0.f) ? rsqrtf(fmaxf(d, 1.f)) : 0.f;
    }
    __syncthreads();
    for (int e = t; e < N_EDGES; e += 1024) {
        int s = ei[e];
        int d = ei[N_EDGES + e];
        atomicAdd(&sA[d * N_NODES + s], -sdeg[s] * sdeg[d]);
    }
    __syncthreads();
    for (int i = t; i < 10000; i += 1024) g_A[i] = sA[i];

    if (t < OUT_C) {
        float va = 0.f, vc = 0.f;
        #pragma unroll
        for (int i = 0; i < 3; i++) {
            float v = vnr[i];
            va += v * avw[i * OUT_C + t] + avb[i * OUT_C + t];
            vc += v * cvw[i * OUT_C + t] + cvb[i * OUT_C + t];
        }
        g_V[t] = va;
        g_V[OUT_C + t] = vc;
    }

    for (int j = t; j < out_size; j += 1024)
        out[j] = (j < 100) ? afb[j] : ((j == 100) ? cfb[0] : 0.f);
}

// ---------------------------------------------------------------------------
// A-tile staging via 16B cp.async (Xh/Xl already fp16 in gmem)
// ---------------------------------------------------------------------------
__device__ __forceinline__ void stage_A_async(u32 buf, int kb, int t) {
    #pragma unroll
    for (int i = 0; i < 4; i++) {
        int idx = t + i * GTHREADS;
        if (idx < 800) {
            int m = idx >> 3, q = idx & 7;          // q = 16B chunk
            size_t w = (size_t)m * (IN_C / 2) + (kb >> 1) + q * 4;
            u32 d = buf + (u32)((m * AROW_W + q * 4) * 4);
            cpasync16(d, g_Xh + w);
            cpasync16(d + ALO_W * 4, g_Xl + w);
        }
    }
    CPASYNC_COMMIT();
}

// ---------------------------------------------------------------------------
// Kernel 2: fp16 2-term tensor-core GEMM  (Y = (Xh + Xl) · fp16(W))
//   KTILE=64, double-buffered, occ 2; A via cp.async, W via reg path
//   (measured-best R9 configuration)
// ---------------------------------------------------------------------------
__global__ __launch_bounds__(GTHREADS, 2)
void gemm_mma(const float* __restrict__ aw,
              const float* __restrict__ cw) {
    extern __shared__ u32 smw[];
    const int t = threadIdx.x;
    const int lane = t & 31, wid = t >> 5;
    const int wm = wid >> 1, wn = wid & 1;
    const bool do_mt1 = (wm < 3);          // rows 112-127: all pad
    const int hk = blockIdx.y;
    const float* Wbase = ((hk >= 3) ? cw : aw) + (size_t)(hk % 3) * IN_C * OUT_C;

    int k0 = (int)(((long long)blockIdx.x * IN_C) / NSPLIT) & ~(KTILE - 1);
    int k1 = (int)(((long long)(blockIdx.x + 1) * IN_C) / NSPLIT) & ~(KTILE - 1);
    const int nch = (k1 - k0) / KTILE;

    float acc[2][4][4];
    #pragma unroll
    for (int mt = 0; mt < 2; mt++)
        #pragma unroll
        for (int nt = 0; nt < 4; nt++)
            #pragma unroll
            for (int q = 0; q < 4; q++) acc[mt][nt][q] = 0.f;

    const u32 sbase = smem_addr_u32(smw);
    const int t2 = lane >> 3, rr = lane & 7;
    const u32 a_off = (u32)(((wm * 32 + rr + (t2 & 1) * 8) * AROW_W + (t2 >> 1) * 4) * 4);
    const u32 b_off = (u32)(BHI_W * 4) +
                      (u32)(((wn * 32 + rr + (t2 >> 1) * 8) * AROW_W + (t2 & 1) * 4) * 4);

    float wr[15];

    // ---- preamble: stage 0 (A via cp.async, W via regs)
    stage_A_async(sbase, k0, t);
    #pragma unroll
    for (int i = 0; i < 15; i++) {
        int idx = t + i * GTHREADS;
        int k = idx / OUT_C, ch = idx - k * OUT_C;
        wr[i] = Wbase[(size_t)(k0 + k) * OUT_C + ch];
    }
    CPASYNC_WAIT();
    __syncthreads();
    {
        u32* sb = smw;
        #pragma unroll
        for (int i = 0; i < 15; i++) {
            int idx = t + i * GTHREADS;
            int k = idx / OUT_C, ch = idx - k * OUT_C;
            ((__half*)(sb + BHI_W))[ch * 72 + k] = __float2half_rn(wr[i]);
        }
    }
    __syncthreads();

    for (int c = 0; c < nch; c++) {
        const u32 stb = sbase + ((c & 1) ? STAGE_W * 4 : 0);
        const u32 stn = sbase + ((c & 1) ? 0 : STAGE_W * 4);
        const bool more = (c + 1 < nch);

        // ---- stage c+1: A cp.async in flight + W gmem->regs
        if (more) {
            int kb = k0 + (c + 1) * KTILE;
            stage_A_async(stn, kb, t);
            #pragma unroll
            for (int i = 0; i < 15; i++) {
                int idx = t + i * GTHREADS;
                int k = idx / OUT_C, ch = idx - k * OUT_C;
                wr[i] = Wbase[(size_t)(kb + k) * OUT_C + ch];
            }
        }

        // ---- HMMA on stage c: 4 k16 steps, 2 terms, f32 acc
        #pragma unroll
        for (int kc = 0; kc < 4; kc++) {
            const u32 ko = kc * 32;
            u32 ah0[4], ah1[4], al0[4], al1[4];
            u32 b0[4], b1[4];
            LDSM4(ah0, stb + a_off + ko);
            if (do_mt1) LDSM4(ah1, stb + a_off + 2304 + ko);
            LDSM4(al0, stb + a_off + 18432 + ko);
            if (do_mt1) LDSM4(al1, stb + a_off + 18432 + 2304 + ko);
            LDSM4(b0, stb + b_off + ko);
            LDSM4(b1, stb + b_off + 2304 + ko);

            const u32* bh[4] = { b0, b0 + 2, b1, b1 + 2 };
            #pragma unroll
            for (int nt = 0; nt < 4; nt++) {
                mma16816(acc[0][nt], ah0, bh[nt]);
                mma16816(acc[0][nt], al0, bh[nt]);
                if (do_mt1) {
                    mma16816(acc[1][nt], ah1, bh[nt]);
                    mma16816(acc[1][nt], al1, bh[nt]);
                }
            }
        }

        // ---- W convert+store for stage c+1, then drain A cp.async
        if (more) {
            u32* sb = smw + ((c + 1) & 1) * STAGE_W;
            #pragma unroll
            for (int i = 0; i < 15; i++) {
                int idx = t + i * GTHREADS;
                int k = idx / OUT_C, ch = idx - k * OUT_C;
                ((__half*)(sb + BHI_W))[ch * 72 + k] = __float2half_rn(wr[i]);
            }
            CPASYNC_WAIT();
        }
        __syncthreads();
    }

    // ---- epilogue: atomicAdd into transposed Yt
    const int r = lane >> 2, cb = (lane & 3) * 2;
    float* Yg = g_Yt + hk * 60 * 100;
    #pragma unroll
    for (int mt = 0; mt < 2; mt++) {
        if (mt == 1 && !do_mt1) break;
        int row = wm * 32 + mt * 16 + r;
        #pragma unroll
        for (int nt = 0; nt < 4; nt++) {
            int col = wn * 32 + nt * 8 + cb;
            if (col < OUT_C) {
                if (row < N_NODES)     atomicAdd(Yg + col * 100 + row,     acc[mt][nt][0]);
                if (row + 8 < N_NODES) atomicAdd(Yg + col * 100 + row + 8, acc[mt][nt][2]);
            }
            if (col + 1 < OUT_C) {
                if (row < N_NODES)     atomicAdd(Yg + (col + 1) * 100 + row,     acc[mt][nt][1]);
                if (row + 8 < N_NODES) atomicAdd(Yg + (col + 1) * 100 + row + 8, acc[mt][nt][3]);
            }
        }
    }
}

// ---------------------------------------------------------------------------
// Kernel 3: emb columns (measured-best form). grid 120 = (h,c); 128 threads.
//   Â rows read as float4 straight from L2 (MLP 25), two-phase:
//   emb[:,h,c] = tanh(y0 + Â(y1 + 2 Â y2) − y2 + b) + vnr
// ---------------------------------------------------------------------------
__global__ void emb3_kernel(const float* __restrict__ acb,
                            const float* __restrict__ ccb) {
    __shared__ float y0[100], y1[100], y2[104], zz[104];
    const int b = blockIdx.x, t = threadIdx.x;
    const int h = b / OUT_C, c = b - OUT_C * h;

    if (t < N_NODES) {
        y0[t] = g_Yt[(h * 180 + c) * 100 + t];
        y1[t] = g_Yt[(h * 180 + 60 + c) * 100 + t];
        y2[t] = g_Yt[(h * 180 + 120 + c) * 100 + t];
    }
    __syncthreads();

    if (t < N_NODES) {
        const float4* Ar = (const float4*)(g_A + t * 100);
        float a0 = 0.f, a1 = 0.f, a2 = 0.f, a3 = 0.f;
        #pragma unroll
        for (int q = 0; q < 25; q++) {
            float4 av = Ar[q];
            a0 = fmaf(av.x, y2[q * 4 + 0], a0);
            a1 = fmaf(av.y, y2[q * 4 + 1], a1);
            a2 = fmaf(av.z, y2[q * 4 + 2], a2);
            a3 = fmaf(av.w, y2[q * 4 + 3], a3);
        }
        zz[t] = fmaf(2.f, (a0 + a1) + (a2 + a3), y1[t]);
    }
    __syncthreads();

    if (t < N_NODES) {
        const float4* Ar = (const float4*)(g_A + t * 100);
        float a0 = 0.f, a1 = 0.f, a2 = 0.f, a3 = 0.f;
        #pragma unroll
        for (int q = 0; q < 25; q++) {
            float4 av = Ar[q];
            a0 = fmaf(av.x, zz[q * 4 + 0], a0);
            a1 = fmaf(av.y, zz[q * 4 + 1], a1);
            a2 = fmaf(av.z, zz[q * 4 + 2], a2);
            a3 = fmaf(av.w, zz[q * 4 + 3], a3);
        }
        float pre = y0[t] + (a0 + a1) + (a2 + a3) - y2[t] + (h ? ccb[c] : acb[c]);
        g_emb[h * 6000 + t * OUT_C + c] = tanhf(pre) + g_V[h * OUT_C + c];
    }
}

// ---------------------------------------------------------------------------
// Kernel 4: heads. 120 blocks x 128 threads, 50 rows each of the 6000-dot
// ---------------------------------------------------------------------------
__global__ void fc_kernel(const float* __restrict__ afw,
                          const float* __restrict__ cfw,
                          float* __restrict__ out, int out_size) {
    __shared__ float ea[50], ec[50];
    __shared__ float red[4];
    const int b = blockIdx.x, t = threadIdx.x;
    const int i0 = b * 50;

    if (t < 50) {
        ea[t] = g_emb[i0 + t];
        ec[t] = g_emb[6000 + i0 + t];
    }
    __syncthreads();

    if (t < 100) {
        float a0 = 0.f, a1 = 0.f;
        #pragma unroll 5
        for (int i = 0; i < 50; i += 2) {
            a0 = fmaf(ea[i],     afw[(size_t)(i0 + i) * 100 + t],     a0);
            a1 = fmaf(ea[i + 1], afw[(size_t)(i0 + i + 1) * 100 + t], a1);
        }
        atomicAdd(&out[t], a0 + a1);
    }

    float v = (t < 50) ? ec[t] * cfw[i0 + t] : 0.f;
    #pragma unroll
    for (int off = 16; off > 0; off >>= 1)
        v += __shfl_down_sync(0xffffffffu, v, off);
    if ((t & 31) == 0) red[t >> 5] = v;
    __syncthreads();
    if (t == 0 && out_size > 100)
        atomicAdd(&out[100], red[0] + red[1] + red[2] + red[3]);
}

// ---------------------------------------------------------------------------
// Launch
// ---------------------------------------------------------------------------
extern "C" void kernel_launch(void* const* d_in, const int* in_sizes, int n_in,
                              void* d_out, int out_size) {
    const float* x   = (const float*)d_in[0];
    const int*   ei  = (const int*)  d_in[1];
    const float* vnr = (const float*)d_in[2];
    const float* aw  = (const float*)d_in[3];
    const float* acb = (const float*)d_in[4];
    const float* cw  = (const float*)d_in[5];
    const float* ccb = (const float*)d_in[6];
    const float* avw = (const float*)d_in[7];
    const float* avb = (const float*)d_in[8];
    const float* cvw = (const float*)d_in[9];
    const float* cvb = (const float*)d_in[10];
    const float* afw = (const float*)d_in[11];
    const float* afb = (const float*)d_in[12];
    const float* cfw = (const float*)d_in[13];
    const float* cfb = (const float*)d_in[14];
    float* out = (float*)d_out;

    static int smem_set = 0;
    if (!smem_set) {
        cudaFuncSetAttribute(gemm_mma, cudaFuncAttributeMaxDynamicSharedMemorySize, SMEM_B);
        smem_set = 1;
    }

    xsplit_kernel<<<6400, 256>>>(x);
    prep_kernel<<<1, 1024>>>(ei, vnr, avw, avb, cvw, cvb, afb, cfb, out, out_size);
    gemm_mma<<<dim3(NSPLIT, 6), GTHREADS, SMEM_B>>>(aw, cw);
    emb3_kernel<<<120, 128>>>(acb, ccb);
    fc_kernel<<<120, 128>>>(afw, cfw, out, out_size);
}